// round 3
// baseline (speedup 1.0000x reference)
#include <cuda_runtime.h>
#include <math.h>

#define NN 4096
#define HH 32
#define ROLLN 200
#define BM 64
#define BK 64
#define SPLITS 8
#define KC (NN / SPLITS)        // 512
#define UPD_ROWS 16
#define UPD_THREADS (UPD_ROWS * 32)

// Persistent state (device globals — no allocation allowed)
__device__ float g_h[NN * HH];
__device__ float g_c[NN * HH];
__device__ float g_M[NN * HH];
__device__ float g_part[SPLITS][NN * HH];

__device__ __forceinline__ float pairsum(unsigned long long u) {
    return __uint_as_float((unsigned)u) + __uint_as_float((unsigned)(u >> 32));
}

// ---------------------------------------------------------------------------
// Init: h = c = 0, M0 = X[0] @ Wx   (one thread per (n, j))
// ---------------------------------------------------------------------------
__global__ __launch_bounds__(256) void init_kernel(const float* __restrict__ X,
                                                   const float* __restrict__ Wx) {
    int idx = blockIdx.x * 256 + threadIdx.x;   // 0 .. NN*HH-1
    int n = idx >> 5;
    int j = idx & 31;
    g_h[idx] = 0.f;
    g_c[idx] = 0.f;
    float mv = 0.f;
#pragma unroll
    for (int k = 0; k < 5; k++)
        mv += X[n * 5 + k] * Wx[k * HH + j];
    g_M[idx] = mv;
}

// ---------------------------------------------------------------------------
// GEMM: g_part[split] = A[rows, ksplit] @ M[ksplit, 32]
// Block: 128 threads, tile BM=64 rows x 32 cols, split-K over SPLITS.
// Thread tile 4 rows x 4 cols, k-paired f32x2 accumulation (FFMA2).
// ---------------------------------------------------------------------------
__global__ __launch_bounds__(128) void gemm_kernel(const float* __restrict__ A) {
    __shared__ float sA[BM][BK + 4];    // pitch 68 (even, %4==0 -> 16B-aligned f4 stores)
    __shared__ float sMT[HH][BK + 2];   // k-transposed M tile, pitch 66 (even)

    const int tid  = threadIdx.x;
    const int row0 = blockIdx.x * BM;
    const int split = blockIdx.y;
    const int jc = tid & 7;             // cols 4*jc .. 4*jc+3
    const int rg = tid >> 3;            // rows 4*rg .. 4*rg+3  (rg in 0..15)

    unsigned long long acc[4][4];
#pragma unroll
    for (int i = 0; i < 4; i++)
#pragma unroll
        for (int c = 0; c < 4; c++) acc[i][c] = 0ull;

    const float* Abase = A + (size_t)row0 * NN + split * KC;

    for (int kc = 0; kc < KC; kc += BK) {
        // Load A tile: 64 rows x 64 k = 1024 float4, 8 per thread
#pragma unroll
        for (int it = 0; it < 8; it++) {
            int f4 = tid + it * 128;
            int r  = f4 >> 4;
            int c4 = (f4 & 15) << 2;
            float4 v = *(const float4*)(Abase + (size_t)r * NN + kc + c4);
            *(float4*)&sA[r][c4] = v;
        }
        // Load M tile transposed: sMT[j][k] = M[k][j]
#pragma unroll
        for (int it = 0; it < 4; it++) {
            int f4 = tid + it * 128;
            int k  = f4 >> 3;
            int j4 = (f4 & 7) << 2;
            float4 v = *(const float4*)&g_M[(split * KC + kc + k) * HH + j4];
            sMT[j4 + 0][k] = v.x;
            sMT[j4 + 1][k] = v.y;
            sMT[j4 + 2][k] = v.z;
            sMT[j4 + 3][k] = v.w;
        }
        __syncthreads();

#pragma unroll 4
        for (int kk = 0; kk < BK; kk += 2) {
            unsigned long long a2[4], m2[4];
#pragma unroll
            for (int i = 0; i < 4; i++)
                a2[i] = *(const unsigned long long*)&sA[4 * rg + i][kk];
#pragma unroll
            for (int c = 0; c < 4; c++)
                m2[c] = *(const unsigned long long*)&sMT[4 * jc + c][kk];
#pragma unroll
            for (int i = 0; i < 4; i++)
#pragma unroll
                for (int c = 0; c < 4; c++)
                    asm("fma.rn.f32x2 %0, %1, %2, %0;"
                        : "+l"(acc[i][c]) : "l"(a2[i]), "l"(m2[c]));
        }
        __syncthreads();
    }

    float* outp = &g_part[split][0];
#pragma unroll
    for (int i = 0; i < 4; i++) {
        float4 v;
        v.x = pairsum(acc[i][0]);
        v.y = pairsum(acc[i][1]);
        v.z = pairsum(acc[i][2]);
        v.w = pairsum(acc[i][3]);
        *(float4*)&outp[(row0 + 4 * rg + i) * HH + 4 * jc] = v;
    }
}

// ---------------------------------------------------------------------------
// Update: reduce split-K partials -> gates -> LSTM cell -> next M (or output).
// One warp per node row (lane = hidden column). Weights in smem, pitch 33
// (conflict-free: bank = (q + m) % 32). Row state exchanged via shuffles.
// ---------------------------------------------------------------------------
__global__ __launch_bounds__(UPD_THREADS) void update_kernel(
    const float* __restrict__ X,
    const float* __restrict__ Wh,
    const float* __restrict__ Wc,
    const float* __restrict__ Wx,
    const float* __restrict__ W_ih,
    const float* __restrict__ W_hh,
    const float* __restrict__ b_ih,
    const float* __restrict__ b_hh,
    const float* __restrict__ W_fc,
    const float* __restrict__ b_fc,
    float* __restrict__ out,
    int t)
{
    __shared__ float sWih[128 * 33];
    __shared__ float sWhh[128 * 33];
    __shared__ float sWh[32 * 33];
    __shared__ float sWc[32 * 33];
    __shared__ float sWx[5 * 32];
    __shared__ float sb[128];

    const int tid = threadIdx.x;
    for (int i = tid; i < 128 * 32; i += UPD_THREADS) {
        int q = i >> 5, m = i & 31;
        sWih[q * 33 + m] = W_ih[i];
        sWhh[q * 33 + m] = W_hh[i];
    }
    for (int i = tid; i < 32 * 32; i += UPD_THREADS) {
        int q = i >> 5, m = i & 31;
        sWh[q * 33 + m] = Wh[i];
        sWc[q * 33 + m] = Wc[i];
    }
    if (tid < 160) sWx[tid] = Wx[tid];
    if (tid < 128) sb[tid] = b_ih[tid] + b_hh[tid];
    __syncthreads();

    const int j  = tid & 31;
    const int r  = tid >> 5;
    const int n  = blockIdx.x * UPD_ROWS + r;
    const int nj = n * HH + j;

    // Reduce split-K partials (fixed order -> deterministic)
    float x = 0.f;
#pragma unroll
    for (int s = 0; s < SPLITS; s++) x += g_part[s][nj];
    float hv = g_h[nj];
    float cv = g_c[nj];

    // gates[q] = sum_m inp[m]*W_ih[q][m] + h[m]*W_hh[q][m] + b_ih[q] + b_hh[q]
    // lane j owns q in {j, 32+j, 64+j, 96+j} == (i, f, g, o) for column j.
    float gi = sb[j], gf = sb[32 + j], gg = sb[64 + j], go = sb[96 + j];
#pragma unroll
    for (int m = 0; m < 32; m++) {
        float xm = __shfl_sync(0xffffffffu, x,  m);
        float hm = __shfl_sync(0xffffffffu, hv, m);
        gi += xm * sWih[j * 33 + m]        + hm * sWhh[j * 33 + m];
        gf += xm * sWih[(32 + j) * 33 + m] + hm * sWhh[(32 + j) * 33 + m];
        gg += xm * sWih[(64 + j) * 33 + m] + hm * sWhh[(64 + j) * 33 + m];
        go += xm * sWih[(96 + j) * 33 + m] + hm * sWhh[(96 + j) * 33 + m];
    }
    float si = 1.f / (1.f + expf(-gi));
    float sf = 1.f / (1.f + expf(-gf));
    float tg = tanhf(gg);
    float so = 1.f / (1.f + expf(-go));
    float cn = sf * cv + si * tg;
    float hn = so * tanhf(cn);
    g_c[nj] = cn;
    g_h[nj] = hn;

    if (t == ROLLN - 1) {
        // out[n] = h_final @ W_fc^T + b_fc
        float v = hn * W_fc[j];
#pragma unroll
        for (int o = 16; o > 0; o >>= 1)
            v += __shfl_xor_sync(0xffffffffu, v, o);
        if (j == 0) out[n] = v + b_fc[0];
    } else {
        // M_next[n][j] = X[t+1][n] @ Wx + h_new @ Wh + c_new @ Wc   (col j)
        const float* xr = X + ((size_t)(t + 1) * NN + n) * 5;
        float mv = 0.f;
#pragma unroll
        for (int k = 0; k < 5; k++) mv += xr[k] * sWx[k * 32 + j];
#pragma unroll
        for (int m = 0; m < 32; m++) {
            float hm = __shfl_sync(0xffffffffu, hn, m);
            float cm = __shfl_sync(0xffffffffu, cn, m);
            mv += hm * sWh[m * 33 + j] + cm * sWc[m * 33 + j];
        }
        g_M[nj] = mv;
    }
}

// ---------------------------------------------------------------------------
extern "C" void kernel_launch(void* const* d_in, const int* in_sizes, int n_in,
                              void* d_out, int out_size) {
    const float* X    = (const float*)d_in[0];
    const float* A    = (const float*)d_in[1];
    const float* Wx   = (const float*)d_in[2];
    const float* Wh   = (const float*)d_in[3];
    const float* Wc   = (const float*)d_in[4];
    const float* W_ih = (const float*)d_in[5];
    const float* W_hh = (const float*)d_in[6];
    const float* b_ih = (const float*)d_in[7];
    const float* b_hh = (const float*)d_in[8];
    const float* W_fc = (const float*)d_in[9];
    const float* b_fc = (const float*)d_in[10];
    float* out = (float*)d_out;

    init_kernel<<<(NN * HH) / 256, 256>>>(X, Wx);

    dim3 ggrid(NN / BM, SPLITS);
    for (int t = 0; t < ROLLN; t++) {
        gemm_kernel<<<ggrid, 128>>>(A);
        update_kernel<<<NN / UPD_ROWS, UPD_THREADS>>>(
            X, Wh, Wc, Wx, W_ih, W_hh, b_ih, b_hh, W_fc, b_fc, out, t);
    }
}

// round 7
// speedup vs baseline: 1.7399x; 1.7399x over previous
#include <cuda_runtime.h>
#include <math.h>

#define NN 4096
#define HH 32
#define ROLLN 200
#define SPLITS 18           // 16 chunks of 228 + 2 chunks of 224 (all 4-aligned)
#define MAXCHUNK 228
#define GROWS 128           // rows per gemm block (= threads per gemm block)
#define UPD_ROWS 32
#define UPD_THREADS (UPD_ROWS * 32)

// Persistent state (device globals — no allocation allowed)
__device__ float g_h[NN * HH];
__device__ float g_c[NN * HH];
__device__ float g_M[NN * HH];
__device__ float g_part[SPLITS][NN * HH];

__device__ __forceinline__ int chunk_start(int s) {
    return (s < 16) ? 228 * s : 3648 + 224 * (s - 16);
}
__device__ __forceinline__ int chunk_size(int s) {
    return (s < 16) ? 228 : 224;
}

// ---------------------------------------------------------------------------
// Init: h = c = 0, M0 = X[0] @ Wx
// ---------------------------------------------------------------------------
__global__ __launch_bounds__(256) void init_kernel(const float* __restrict__ X,
                                                   const float* __restrict__ Wx) {
    int idx = blockIdx.x * 256 + threadIdx.x;   // 0 .. NN*HH-1
    int n = idx >> 5;
    int j = idx & 31;
    g_h[idx] = 0.f;
    g_c[idx] = 0.f;
    float mv = 0.f;
#pragma unroll
    for (int k = 0; k < 5; k++)
        mv += X[n * 5 + k] * Wx[k * HH + j];
    g_M[idx] = mv;
}

// ---------------------------------------------------------------------------
// GEMM (row-stationary): g_part[s] = A[:, chunk_s] @ M[chunk_s, :]
// One thread = one A row x ALL 32 output columns. A read directly from
// global (L2-resident, per-thread sequential -> L1 line reuse). M chunk
// staged in smem; every inner-loop LDS.128 is a warp-broadcast (free-ish
// crossbar). FFMA2 paired over column pairs -> acc halves ARE the outputs.
// ---------------------------------------------------------------------------
__global__ __launch_bounds__(GROWS) void gemm_kernel(const float* __restrict__ A) {
    __shared__ float sM[MAXCHUNK * HH];   // <= 28.5 KB

    const int tid = threadIdx.x;
    const int row = blockIdx.x * GROWS + tid;
    const int s = blockIdx.y;
    const int kstart = chunk_start(s);
    const int ksize = chunk_size(s);

    // Stage M chunk (contiguous in g_M) -> smem, vectorized
    {
        const float4* src = (const float4*)(g_M + kstart * HH);
        float4* dst = (float4*)sM;
        int nf4 = (ksize * HH) >> 2;
        for (int i = tid; i < nf4; i += GROWS) dst[i] = src[i];
    }
    __syncthreads();

    unsigned long long acc[16];           // acc[q] = cols (2q, 2q+1)
#pragma unroll
    for (int q = 0; q < 16; q++) acc[q] = 0ull;

    const float* arow = A + (size_t)row * NN + kstart;
    const int nk4 = ksize >> 2;

    float4 a4 = *(const float4*)(arow);
    for (int k4 = 0; k4 < nk4; k4++) {
        // branch-free prefetch (last iter re-reads in-bounds tail)
        int kn = 4 * k4 + 4;
        if (kn > ksize - 4) kn = ksize - 4;
        float4 an = *(const float4*)(arow + kn);

        float av[4] = {a4.x, a4.y, a4.z, a4.w};
#pragma unroll
        for (int u = 0; u < 4; u++) {
            unsigned long long a2;
            asm("mov.b64 %0, {%1, %1};" : "=l"(a2) : "f"(av[u]));
            const ulonglong2* mp = (const ulonglong2*)(sM + (4 * k4 + u) * HH);
#pragma unroll
            for (int i = 0; i < 8; i++) {
                ulonglong2 mm = mp[i];   // LDS.128 broadcast: cols 4i..4i+3
                asm("fma.rn.f32x2 %0, %1, %2, %0;"
                    : "+l"(acc[2 * i]) : "l"(a2), "l"(mm.x));
                asm("fma.rn.f32x2 %0, %1, %2, %0;"
                    : "+l"(acc[2 * i + 1]) : "l"(a2), "l"(mm.y));
            }
        }
        a4 = an;
    }

    // acc halves are directly out[row][0..31]
    ulonglong2* op = (ulonglong2*)(&g_part[s][(size_t)row * HH]);
#pragma unroll
    for (int i = 0; i < 8; i++)
        op[i] = make_ulonglong2(acc[2 * i], acc[2 * i + 1]);
}

// ---------------------------------------------------------------------------
// Update: reduce split-K partials -> gates -> LSTM cell -> next M (or output).
// One warp per node row (lane = hidden column). Weights in smem (pitch 33:
// conflict-free). Row state exchanged via shuffles.
// ---------------------------------------------------------------------------
__global__ __launch_bounds__(UPD_THREADS) void update_kernel(
    const float* __restrict__ X,
    const float* __restrict__ Wh,
    const float* __restrict__ Wc,
    const float* __restrict__ Wx,
    const float* __restrict__ W_ih,
    const float* __restrict__ W_hh,
    const float* __restrict__ b_ih,
    const float* __restrict__ b_hh,
    const float* __restrict__ W_fc,
    const float* __restrict__ b_fc,
    float* __restrict__ out,
    int t)
{
    __shared__ float sWih[128 * 33];
    __shared__ float sWhh[128 * 33];
    __shared__ float sWh[32 * 33];
    __shared__ float sWc[32 * 33];
    __shared__ float sWx[5 * 32];
    __shared__ float sb[128];

    const int tid = threadIdx.x;
    for (int i = tid; i < 128 * 32; i += UPD_THREADS) {
        int q = i >> 5, m = i & 31;
        sWih[q * 33 + m] = W_ih[i];
        sWhh[q * 33 + m] = W_hh[i];
    }
    for (int i = tid; i < 32 * 32; i += UPD_THREADS) {
        int q = i >> 5, m = i & 31;
        sWh[q * 33 + m] = Wh[i];
        sWc[q * 33 + m] = Wc[i];
    }
    if (tid < 160) sWx[tid] = Wx[tid];
    if (tid < 128) sb[tid] = b_ih[tid] + b_hh[tid];
    __syncthreads();

    const int j  = tid & 31;
    const int r  = tid >> 5;
    const int n  = blockIdx.x * UPD_ROWS + r;
    const int nj = n * HH + j;

    // Reduce split-K partials (fixed order -> deterministic)
    float x = 0.f;
#pragma unroll
    for (int s = 0; s < SPLITS; s++) x += g_part[s][nj];
    float hv = g_h[nj];
    float cv = g_c[nj];

    // lane j owns gate rows {j, 32+j, 64+j, 96+j} == (i, f, g, o) for col j
    float gi = sb[j], gf = sb[32 + j], gg = sb[64 + j], go = sb[96 + j];
#pragma unroll
    for (int m = 0; m < 32; m++) {
        float xm = __shfl_sync(0xffffffffu, x,  m);
        float hm = __shfl_sync(0xffffffffu, hv, m);
        gi += xm * sWih[j * 33 + m]        + hm * sWhh[j * 33 + m];
        gf += xm * sWih[(32 + j) * 33 + m] + hm * sWhh[(32 + j) * 33 + m];
        gg += xm * sWih[(64 + j) * 33 + m] + hm * sWhh[(64 + j) * 33 + m];
        go += xm * sWih[(96 + j) * 33 + m] + hm * sWhh[(96 + j) * 33 + m];
    }
    float si = 1.f / (1.f + expf(-gi));
    float sf = 1.f / (1.f + expf(-gf));
    float tg = tanhf(gg);
    float so = 1.f / (1.f + expf(-go));
    float cn = sf * cv + si * tg;
    float hn = so * tanhf(cn);
    g_c[nj] = cn;
    g_h[nj] = hn;

    if (t == ROLLN - 1) {
        // out[n] = h_final @ W_fc^T + b_fc
        float v = hn * W_fc[j];
#pragma unroll
        for (int o = 16; o > 0; o >>= 1)
            v += __shfl_xor_sync(0xffffffffu, v, o);
        if (j == 0) out[n] = v + b_fc[0];
    } else {
        // M_next[n][j] = X[t+1][n] @ Wx + h_new @ Wh + c_new @ Wc   (col j)
        const float* xr = X + ((size_t)(t + 1) * NN + n) * 5;
        float mv = 0.f;
#pragma unroll
        for (int k = 0; k < 5; k++) mv += xr[k] * sWx[k * 32 + j];
#pragma unroll
        for (int m = 0; m < 32; m++) {
            float hm = __shfl_sync(0xffffffffu, hn, m);
            float cm = __shfl_sync(0xffffffffu, cn, m);
            mv += hm * sWh[m * 33 + j] + cm * sWc[m * 33 + j];
        }
        g_M[nj] = mv;
    }
}

// ---------------------------------------------------------------------------
extern "C" void kernel_launch(void* const* d_in, const int* in_sizes, int n_in,
                              void* d_out, int out_size) {
    const float* X    = (const float*)d_in[0];
    const float* A    = (const float*)d_in[1];
    const float* Wx   = (const float*)d_in[2];
    const float* Wh   = (const float*)d_in[3];
    const float* Wc   = (const float*)d_in[4];
    const float* W_ih = (const float*)d_in[5];
    const float* W_hh = (const float*)d_in[6];
    const float* b_ih = (const float*)d_in[7];
    const float* b_hh = (const float*)d_in[8];
    const float* W_fc = (const float*)d_in[9];
    const float* b_fc = (const float*)d_in[10];
    float* out = (float*)d_out;

    init_kernel<<<(NN * HH) / 256, 256>>>(X, Wx);

    dim3 ggrid(NN / GROWS, SPLITS);
    for (int t = 0; t < ROLLN; t++) {
        gemm_kernel<<<ggrid, GROWS>>>(A);
        update_kernel<<<NN / UPD_ROWS, UPD_THREADS>>>(
            X, Wh, Wc, Wx, W_ih, W_hh, b_ih, b_hh, W_fc, b_fc, out, t);
    }
}

// round 9
// speedup vs baseline: 4.3037x; 2.4735x over previous
#include <cuda_runtime.h>
#include <cuda_bf16.h>
#include <math.h>
#include <stdint.h>

#define NN 4096
#define HH 32
#define ROLLN 200
#define KSPLITS 4
#define ROWTILES 32            // 4096 / 128
#define NCH_TOT 64             // K chunks of 64 over 4096
#define NCH_PER 16             // chunks per CTA (K=1024 per split)
#define ATILE_BYTES 16384      // 128 rows x 64 k x 2B (bf16), SW128 image
#define ATILE_ELEMS 8192
#define BTILE_BYTES 4096       // 32 n x 64 k x 2B
#define BTILE_ELEMS 2048
#define GEMM_THREADS 256
#define UPD_ROWS 32
#define UPD_THREADS (UPD_ROWS * 32)

// smem layout (gemm)
#define MB_FULL0 0
#define SMEM_BUF 1024
#define BUF_STRIDE 40960
#define OFF_AHI 0
#define OFF_ALO 16384
#define OFF_BHI 32768
#define OFF_BLO 36864
#define SMEM_DYN (SMEM_BUF + 2 * BUF_STRIDE)   // 82944

// Persistent state (device globals — no allocation allowed)
__device__ float g_h[NN * HH];
__device__ float g_c[NN * HH];
__device__ float g_part[KSPLITS][NN * HH];
__device__ __align__(1024) __nv_bfloat16 g_Ahi[ROWTILES * NCH_TOT * ATILE_ELEMS];
__device__ __align__(1024) __nv_bfloat16 g_Alo[ROWTILES * NCH_TOT * ATILE_ELEMS];
__device__ __align__(1024) __nv_bfloat16 g_Bhi[NCH_TOT * BTILE_ELEMS];
__device__ __align__(1024) __nv_bfloat16 g_Blo[NCH_TOT * BTILE_ELEMS];

__device__ __forceinline__ uint32_t swz(uint32_t b) { return b ^ ((b >> 3) & 0x70); }

__device__ __forceinline__ uint32_t smem_u32(const void* p) {
    uint32_t a;
    asm("{ .reg .u64 t; cvta.to.shared.u64 t, %1; cvt.u32.u64 %0, t; }" : "=r"(a) : "l"(p));
    return a;
}
__device__ __forceinline__ void mbar_init(uint32_t a, uint32_t c) {
    asm volatile("mbarrier.init.shared.b64 [%0], %1;" :: "r"(a), "r"(c) : "memory");
}
__device__ __forceinline__ void mbar_expect(uint32_t a, uint32_t n) {
    asm volatile("mbarrier.arrive.expect_tx.shared.b64 _, [%0], %1;" :: "r"(a), "r"(n) : "memory");
}
__device__ __forceinline__ void mbar_wait(uint32_t mbar, uint32_t parity) {
    asm volatile(
        "{\n\t.reg .pred P1;\n\t"
        "WL_%=:\n\t"
        "mbarrier.try_wait.parity.acquire.cta.shared::cta.b64 P1, [%0], %1, 0x989680;\n\t"
        "@P1 bra.uni WD_%=;\n\t"
        "bra.uni WL_%=;\n\t"
        "WD_%=:\n\t}"
        :: "r"(mbar), "r"(parity) : "memory");
}
__device__ __forceinline__ void bulk_g2s(uint32_t dst, const void* src, uint32_t bytes, uint32_t mbar) {
    asm volatile(
        "cp.async.bulk.shared::cluster.global.mbarrier::complete_tx::bytes [%0], [%1], %2, [%3];"
        :: "r"(dst), "l"(src), "r"(bytes), "r"(mbar) : "memory");
}
__device__ __forceinline__ void ldsm4(uint32_t* r, uint32_t addr) {
    asm volatile("ldmatrix.sync.aligned.m8n8.x4.shared.b16 {%0,%1,%2,%3}, [%4];"
                 : "=r"(r[0]), "=r"(r[1]), "=r"(r[2]), "=r"(r[3]) : "r"(addr));
}
__device__ __forceinline__ void hmma(float* c, const uint32_t* a, uint32_t b0, uint32_t b1) {
    asm volatile(
        "mma.sync.aligned.m16n8k16.row.col.f32.bf16.bf16.f32 "
        "{%0,%1,%2,%3}, {%4,%5,%6,%7}, {%8,%9}, {%0,%1,%2,%3};"
        : "+f"(c[0]), "+f"(c[1]), "+f"(c[2]), "+f"(c[3])
        : "r"(a[0]), "r"(a[1]), "r"(a[2]), "r"(a[3]), "r"(b0), "r"(b1));
}

// ---------------------------------------------------------------------------
// One-time: split A into pre-swizzled, pre-tiled bf16 hi/lo images
// ---------------------------------------------------------------------------
__global__ __launch_bounds__(256) void convA_kernel(const float* __restrict__ A) {
    int idx = blockIdx.x * 256 + threadIdx.x;     // 0 .. NN*NN-1
    int r = idx >> 12;
    int k = idx & 4095;
    float v = A[idx];
    __nv_bfloat16 hi = __float2bfloat16(v);
    __nv_bfloat16 lo = __float2bfloat16(v - __bfloat162float(hi));
    int tile = (r >> 7) * NCH_TOT + (k >> 6);
    uint32_t off = swz((uint32_t)((r & 127) * 128 + (k & 63) * 2)) >> 1;
    g_Ahi[(size_t)tile * ATILE_ELEMS + off] = hi;
    g_Alo[(size_t)tile * ATILE_ELEMS + off] = lo;
}

// ---------------------------------------------------------------------------
// Init: h = c = 0, M0 = X[0] @ Wx  -> swizzled bf16 hi/lo B tiles
// B tile layout: [chunk kc][n-col j (0..31)][k-in-chunk (0..63)], SW128 rows
// ---------------------------------------------------------------------------
__global__ __launch_bounds__(256) void init_kernel(const float* __restrict__ X,
                                                   const float* __restrict__ Wx) {
    int idx = blockIdx.x * 256 + threadIdx.x;     // 0 .. NN*HH-1
    int n = idx >> 5;
    int j = idx & 31;
    g_h[idx] = 0.f;
    g_c[idx] = 0.f;
    float mv = 0.f;
#pragma unroll
    for (int k = 0; k < 5; k++)
        mv += X[n * 5 + k] * Wx[k * HH + j];
    __nv_bfloat16 hi = __float2bfloat16(mv);
    __nv_bfloat16 lo = __float2bfloat16(mv - __bfloat162float(hi));
    int kc = n >> 6;
    uint32_t off = swz((uint32_t)(j * 128 + (n & 63) * 2)) >> 1;
    g_Bhi[kc * BTILE_ELEMS + off] = hi;
    g_Blo[kc * BTILE_ELEMS + off] = lo;
}

// ---------------------------------------------------------------------------
// HMMA GEMM: g_part[split] = A[128-row tile, ksplit] @ M[ksplit, 32]
// bf16-split 3-product (AhiBhi + AhiBlo + AloBhi) into fp32 accumulators.
// Double-buffered cp.async.bulk from pre-tiled swizzled global images.
// 8 warps x 16 rows; ldmatrix conflict-free via SW128.
// ---------------------------------------------------------------------------
__device__ __forceinline__ void copy_chunk(uint32_t sb, int b, int rowtile, int chg) {
    uint32_t base = sb + SMEM_BUF + b * BUF_STRIDE;
    uint32_t mbar = sb + MB_FULL0 + b * 8;
    mbar_expect(mbar, 2 * ATILE_BYTES + 2 * BTILE_BYTES);
    bulk_g2s(base + OFF_AHI, g_Ahi + ((size_t)rowtile * NCH_TOT + chg) * ATILE_ELEMS,
             ATILE_BYTES, mbar);
    bulk_g2s(base + OFF_ALO, g_Alo + ((size_t)rowtile * NCH_TOT + chg) * ATILE_ELEMS,
             ATILE_BYTES, mbar);
    bulk_g2s(base + OFF_BHI, g_Bhi + (size_t)chg * BTILE_ELEMS, BTILE_BYTES, mbar);
    bulk_g2s(base + OFF_BLO, g_Blo + (size_t)chg * BTILE_ELEMS, BTILE_BYTES, mbar);
}

__global__ __launch_bounds__(GEMM_THREADS) void gemm_tc() {
    extern __shared__ char smem[];
    uint32_t sb = smem_u32(smem);
    const int tid = threadIdx.x;
    const int wid = tid >> 5;
    const int lid = tid & 31;
    const int rowtile = blockIdx.x;
    const int split = blockIdx.y;

    if (tid == 0) {
        mbar_init(sb + MB_FULL0, 1);
        mbar_init(sb + MB_FULL0 + 8, 1);
    }
    __syncthreads();

    float acc[16];
#pragma unroll
    for (int q = 0; q < 16; q++) acc[q] = 0.f;

    // per-lane fragment address components
    const int arow = (wid << 4) + (lid & 15);
    const uint32_t aRowOff = (uint32_t)arow * 128;
    const uint32_t aSx = (uint32_t)(arow & 7) << 4;
    const uint32_t aHalf = (uint32_t)(lid >> 4) << 4;
    const int bn = ((lid >> 4) << 3) + (lid & 7);       // n rows 0..15
    const uint32_t bRowOff = (uint32_t)bn * 128;
    const uint32_t bSx = (uint32_t)(lid & 7) << 4;
    const uint32_t bHalf = (uint32_t)((lid >> 3) & 1) << 4;

    const int ch0 = split * NCH_PER;
    int fph0 = 0, fph1 = 0;
    if (tid == 0) copy_chunk(sb, 0, rowtile, ch0);

    for (int i = 0; i < NCH_PER; i++) {
        const int b = i & 1;
        if (tid == 0 && i + 1 < NCH_PER)
            copy_chunk(sb, b ^ 1, rowtile, ch0 + i + 1);   // buffer freed by prev sync

        if (b == 0) { mbar_wait(sb + MB_FULL0, fph0); fph0 ^= 1; }
        else        { mbar_wait(sb + MB_FULL0 + 8, fph1); fph1 ^= 1; }

        const uint32_t base = sb + SMEM_BUF + b * BUF_STRIDE;
        const uint32_t aBase = base + OFF_AHI + aRowOff;
        const uint32_t aBaseLo = base + OFF_ALO + aRowOff;
        const uint32_t bBaseHi = base + OFF_BHI + bRowOff;
        const uint32_t bBaseLo = base + OFF_BLO + bRowOff;

#pragma unroll
        for (int ks = 0; ks < 4; ks++) {
            const uint32_t ak = ((uint32_t)(ks << 5) | aHalf) ^ aSx;
            const uint32_t bk = ((uint32_t)(ks << 5) | bHalf) ^ bSx;
            uint32_t ah[4], al[4], bh[8], bl[8];
            ldsm4(ah, aBase + ak);
            ldsm4(al, aBaseLo + ak);
            ldsm4(&bh[0], bBaseHi + bk);
            ldsm4(&bh[4], bBaseHi + 16 * 128 + bk);
            ldsm4(&bl[0], bBaseLo + bk);
            ldsm4(&bl[4], bBaseLo + 16 * 128 + bk);
#pragma unroll
            for (int nt = 0; nt < 4; nt++) {
                float* C = acc + nt * 4;
                hmma(C, ah, bh[2 * nt], bh[2 * nt + 1]);
                hmma(C, ah, bl[2 * nt], bl[2 * nt + 1]);
                hmma(C, al, bh[2 * nt], bh[2 * nt + 1]);
            }
        }
        __syncthreads();
    }

    // Epilogue: c0,c1 -> (row g, n=tg*2,+1); c2,c3 -> row g+8
    const int g = lid >> 2, tg = lid & 3;
    const int row = rowtile * 128 + (wid << 4) + g;
    float* op = &g_part[split][0];
#pragma unroll
    for (int nt = 0; nt < 4; nt++) {
        int n = nt * 8 + tg * 2;
        *(float2*)&op[(size_t)row * HH + n]       = make_float2(acc[nt * 4], acc[nt * 4 + 1]);
        *(float2*)&op[(size_t)(row + 8) * HH + n] = make_float2(acc[nt * 4 + 2], acc[nt * 4 + 3]);
    }
}

// ---------------------------------------------------------------------------
// Update: reduce 4 split-K partials -> gates -> LSTM -> next M (bf16 hi/lo,
// swizzled tiles, via smem transpose) or final output.
// ---------------------------------------------------------------------------
__global__ __launch_bounds__(UPD_THREADS) void update_kernel(
    const float* __restrict__ X,
    const float* __restrict__ Wh,
    const float* __restrict__ Wc,
    const float* __restrict__ Wx,
    const float* __restrict__ W_ih,
    const float* __restrict__ W_hh,
    const float* __restrict__ b_ih,
    const float* __restrict__ b_hh,
    const float* __restrict__ W_fc,
    const float* __restrict__ b_fc,
    float* __restrict__ out,
    int t)
{
    __shared__ float sWih[128 * 33];
    __shared__ float sWhh[128 * 33];
    __shared__ float sWh[32 * 33];
    __shared__ float sWc[32 * 33];
    __shared__ float sWx[5 * 32];
    __shared__ float sb[128];
    __shared__ float smv[32 * 33];

    const int tid = threadIdx.x;
    for (int i = tid; i < 128 * 32; i += UPD_THREADS) {
        int q = i >> 5, m = i & 31;
        sWih[q * 33 + m] = W_ih[i];
        sWhh[q * 33 + m] = W_hh[i];
    }
    for (int i = tid; i < 32 * 32; i += UPD_THREADS) {
        int q = i >> 5, m = i & 31;
        sWh[q * 33 + m] = Wh[i];
        sWc[q * 33 + m] = Wc[i];
    }
    if (tid < 160) sWx[tid] = Wx[tid];
    if (tid < 128) sb[tid] = b_ih[tid] + b_hh[tid];
    __syncthreads();

    const int j  = tid & 31;
    const int r  = tid >> 5;
    const int n  = blockIdx.x * UPD_ROWS + r;
    const int nj = n * HH + j;

    float x = g_part[0][nj] + g_part[1][nj] + g_part[2][nj] + g_part[3][nj];
    float hv = g_h[nj];
    float cv = g_c[nj];

    float gi = sb[j], gf = sb[32 + j], gg = sb[64 + j], go = sb[96 + j];
#pragma unroll
    for (int m = 0; m < 32; m++) {
        float xm = __shfl_sync(0xffffffffu, x,  m);
        float hm = __shfl_sync(0xffffffffu, hv, m);
        gi += xm * sWih[j * 33 + m]        + hm * sWhh[j * 33 + m];
        gf += xm * sWih[(32 + j) * 33 + m] + hm * sWhh[(32 + j) * 33 + m];
        gg += xm * sWih[(64 + j) * 33 + m] + hm * sWhh[(64 + j) * 33 + m];
        go += xm * sWih[(96 + j) * 33 + m] + hm * sWhh[(96 + j) * 33 + m];
    }
    float si = 1.f / (1.f + expf(-gi));
    float sf = 1.f / (1.f + expf(-gf));
    float tg = tanhf(gg);
    float so = 1.f / (1.f + expf(-go));
    float cn = sf * cv + si * tg;
    float hn = so * tanhf(cn);
    g_c[nj] = cn;
    g_h[nj] = hn;

    if (t == ROLLN - 1) {
        float v = hn * W_fc[j];
#pragma unroll
        for (int o = 16; o > 0; o >>= 1)
            v += __shfl_xor_sync(0xffffffffu, v, o);
        if (j == 0) out[n] = v + b_fc[0];
    } else {
        const float* xr = X + ((size_t)(t + 1) * NN + n) * 5;
        float mv = 0.f;
#pragma unroll
        for (int k = 0; k < 5; k++) mv += xr[k] * sWx[k * 32 + j];
#pragma unroll
        for (int m = 0; m < 32; m++) {
            float hm = __shfl_sync(0xffffffffu, hn, m);
            float cm = __shfl_sync(0xffffffffu, cn, m);
            mv += hm * sWh[m * 33 + j] + cm * sWc[m * 33 + j];
        }
        // transpose through smem so bf16 tile stores are warp-contiguous
        smv[r * 33 + j] = mv;
        __syncthreads();
        float tv = smv[j * 33 + r];                  // node n2, column r
        int n2 = blockIdx.x * UPD_ROWS + j;
        __nv_bfloat16 hi = __float2bfloat16(tv);
        __nv_bfloat16 lo = __float2bfloat16(tv - __bfloat162float(hi));
        int kc = n2 >> 6;
        uint32_t off = swz((uint32_t)(r * 128 + (n2 & 63) * 2)) >> 1;
        g_Bhi[kc * BTILE_ELEMS + off] = hi;
        g_Blo[kc * BTILE_ELEMS + off] = lo;
    }
}

// ---------------------------------------------------------------------------
extern "C" void kernel_launch(void* const* d_in, const int* in_sizes, int n_in,
                              void* d_out, int out_size) {
    const float* X    = (const float*)d_in[0];
    const float* A    = (const float*)d_in[1];
    const float* Wx   = (const float*)d_in[2];
    const float* Wh   = (const float*)d_in[3];
    const float* Wc   = (const float*)d_in[4];
    const float* W_ih = (const float*)d_in[5];
    const float* W_hh = (const float*)d_in[6];
    const float* b_ih = (const float*)d_in[7];
    const float* b_hh = (const float*)d_in[8];
    const float* W_fc = (const float*)d_in[9];
    const float* b_fc = (const float*)d_in[10];
    float* out = (float*)d_out;

    cudaFuncSetAttribute(gemm_tc, cudaFuncAttributeMaxDynamicSharedMemorySize, SMEM_DYN);

    convA_kernel<<<(NN * NN) / 256, 256>>>(A);
    init_kernel<<<(NN * HH) / 256, 256>>>(X, Wx);

    dim3 ggrid(ROWTILES, KSPLITS);
    for (int t = 0; t < ROLLN; t++) {
        gemm_tc<<<ggrid, GEMM_THREADS, SMEM_DYN>>>();
        update_kernel<<<NN / UPD_ROWS, UPD_THREADS>>>(
            X, Wh, Wc, Wx, W_ih, W_hh, b_ih, b_hh, W_fc, b_fc, out, t);
    }
}